// round 16
// baseline (speedup 1.0000x reference)
#include <cuda_runtime.h>
#include <cuda_fp16.h>
#include <cstdint>

// y = x @ w + b  (exact collapse of the memristor model; G_off / K_V / k_g all
// cancel).  2-term fp16-split GEMM on mma.sync tensor cores:
//   y = xh@wh + xl@wh   (x = xh+xl exact: xh = 10-mantissa-bit truncation,
//   fp16-representable; only w-rounding error ~2e-4)
// Grid 256 = 128 output tiles (8 row-blk x 16 col-blk, 16x32 each) x 2 k-halves.
// Each CTA: half of K (512), 16 warps x 32-k slices, intra-CTA smem reduce.
// Pair combine: per-pair ticket; first CTA stores its 2KB partial and exits,
// last CTA adds the peer partial + bias.  No spinning, no global barrier.

#define NIN 1024
#define NOUT 512
#define BATCH 128
#define NTHR 512

#define XST 520    // halfs/row (1040B): word stride 260 = 4 mod 32 -> frag reads ok
#define WST 522    // halfs/row (1044B): STS banks 5n distinct; frag reads ok
#define RST 528    // reduce: 16x33 floats per warp

#define OFF_XHI 0
#define OFF_XLO (OFF_XHI + 16 * XST)            // 8320
#define OFF_W   (OFF_XLO + 16 * XST)            // 16640
#define SMEM_HALFS (OFF_W + 32 * WST)           // 33344 halfs = 66688 B
#define SMEM_BYTES (SMEM_HALFS * 2)             // 2 CTAs/SM: 133 KB < 227 KB

__device__ float g_partial[256 * 512];          // [pair][h][512] = 512 KB
__device__ unsigned g_tick[128];                // per-pair monotonic tickets

__device__ __forceinline__ uint32_t packh(float a, float b) {
    __half2 h = __floats2half2_rn(a, b);        // a -> low 16 bits
    return *reinterpret_cast<uint32_t*>(&h);
}
__device__ __forceinline__ uint64_t pack64(uint32_t lo, uint32_t hi) {
    uint64_t r; asm("mov.b64 %0, {%1, %2};" : "=l"(r) : "r"(lo), "r"(hi)); return r;
}
__device__ __forceinline__ float trunc10(float x) {   // top 10 mantissa bits
    return __uint_as_float(__float_as_uint(x) & 0xFFFFE000u);
}
__device__ __forceinline__ void mma_f16(float* c, const uint32_t* a, const uint32_t* b) {
    asm volatile(
        "mma.sync.aligned.m16n8k16.row.col.f32.f16.f16.f32 "
        "{%0,%1,%2,%3}, {%4,%5,%6,%7}, {%8,%9}, {%0,%1,%2,%3};"
        : "+f"(c[0]), "+f"(c[1]), "+f"(c[2]), "+f"(c[3])
        : "r"(a[0]), "r"(a[1]), "r"(a[2]), "r"(a[3]), "r"(b[0]), "r"(b[1]));
}

__global__ __launch_bounds__(NTHR, 2) void fused_kernel(
    const float* __restrict__ X, const float* __restrict__ W,
    const float* __restrict__ B, float* __restrict__ out)
{
    extern __shared__ __half sm[];
    __half* Xhi = sm + OFF_XHI;
    __half* Xlo = sm + OFF_XLO;
    __half* Wn  = sm + OFF_W;

    const int t = threadIdx.x, bid = blockIdx.x;
    const int warp = t >> 5, lane = t & 31;
    const int g  = lane >> 2;          // group row 0..7
    const int tq = lane & 3;           // thread-in-group 0..3
    const int h    = bid & 1;          // k-half 0/1
    const int pair = bid >> 1;         // 0..127
    const int r0 = (pair >> 4) * 16;   // row block 0..7
    const int c0 = (pair & 15) * 32;   // col block 0..15
    const int k0 = h * 512;

    // ---- fill X: 16 rows x 512 k -> xh (exact trunc) + xl (exact residual).
    //      16*128 float4 = 2048 slots = 4 iters of 512 threads. ----
    #pragma unroll
    for (int i = 0; i < 4; ++i) {
        int idx = t + i * NTHR;                 // 0..2047
        int kq = idx & 127, row = idx >> 7;     // row 0..15
        float4 xv = *reinterpret_cast<const float4*>(&X[(r0 + row) * NIN + k0 + 4 * kq]);
        float h0 = trunc10(xv.x), h1 = trunc10(xv.y);
        float h2 = trunc10(xv.z), h3 = trunc10(xv.w);
        int e = row * XST + 4 * kq;             // byte 1040*row + 8*kq: 8B-aligned
        *reinterpret_cast<uint64_t*>(&Xhi[e]) = pack64(packh(h0, h1), packh(h2, h3));
        *reinterpret_cast<uint64_t*>(&Xlo[e]) =
            pack64(packh(xv.x - h0, xv.y - h1), packh(xv.z - h2, xv.w - h3));
    }
    // ---- fill W: 512 k x 32 n -> [n][k] fp16 pairs (round-to-nearest).
    //      256 kp * 32 n = 8192 slots = 16 iters. ----
    #pragma unroll
    for (int i = 0; i < 16; ++i) {
        int idx = t + i * NTHR;                 // 0..8191
        int n = idx & 31, kp = idx >> 5;        // kp 0..255; lanes: consecutive n
        float w0 = W[(k0 + 2 * kp) * NOUT + c0 + n];
        float w1 = W[(k0 + 2 * kp + 1) * NOUT + c0 + n];
        *reinterpret_cast<uint32_t*>(&Wn[n * WST + 2 * kp]) = packh(w0, w1);
    }
    __syncthreads();

    // ---- compute: warp = full 16x32 tile, k slice [warp*32, warp*32+32) ----
    float acc[4][4];
    #pragma unroll
    for (int j = 0; j < 4; ++j)
        #pragma unroll
        for (int q = 0; q < 4; ++q) acc[j][q] = 0.f;

    const int arow0 = g * XST;
    const int arow1 = arow0 + 8 * XST;

    #pragma unroll
    for (int kk = 0; kk < 2; ++kk) {
        const int kb = warp * 32 + kk * 16 + 2 * tq;
        uint32_t ah[4], al[4];
        ah[0] = *reinterpret_cast<const uint32_t*>(&Xhi[arow0 + kb]);
        ah[1] = *reinterpret_cast<const uint32_t*>(&Xhi[arow1 + kb]);
        ah[2] = *reinterpret_cast<const uint32_t*>(&Xhi[arow0 + kb + 8]);
        ah[3] = *reinterpret_cast<const uint32_t*>(&Xhi[arow1 + kb + 8]);
        al[0] = *reinterpret_cast<const uint32_t*>(&Xlo[arow0 + kb]);
        al[1] = *reinterpret_cast<const uint32_t*>(&Xlo[arow1 + kb]);
        al[2] = *reinterpret_cast<const uint32_t*>(&Xlo[arow0 + kb + 8]);
        al[3] = *reinterpret_cast<const uint32_t*>(&Xlo[arow1 + kb + 8]);

        uint32_t bh[4][2];
        #pragma unroll
        for (int j = 0; j < 4; ++j) {
            const int brow = (8 * j + g) * WST;
            bh[j][0] = *reinterpret_cast<const uint32_t*>(&Wn[brow + kb]);
            bh[j][1] = *reinterpret_cast<const uint32_t*>(&Wn[brow + kb + 8]);
        }
        #pragma unroll
        for (int j = 0; j < 4; ++j) mma_f16(acc[j], ah, bh[j]);
        #pragma unroll
        for (int j = 0; j < 4; ++j) mma_f16(acc[j], al, bh[j]);
    }

    // ---- intra-CTA reduce over the 16 k-slices (smem, fixed order) ----
    __syncthreads();                            // tiles no longer read
    float* red = reinterpret_cast<float*>(sm);  // 16 warps x 528 floats = 33.8 KB
    #pragma unroll
    for (int j = 0; j < 4; ++j)
        #pragma unroll
        for (int q = 0; q < 4; ++q) {
            int row = g + 8 * (q >> 1);
            int col = 8 * j + 2 * tq + (q & 1);
            red[warp * RST + row * 33 + col] = acc[j][q];
        }
    __syncthreads();

    // thread t owns output (row = t>>5, col = t&31) of this 16x32 tile
    float v;
    {
        int row = t >> 5, col = t & 31;
        float s[16];
        #pragma unroll
        for (int w = 0; w < 16; ++w)
            s[w] = red[w * RST + row * 33 + col];
        #pragma unroll
        for (int st = 1; st < 16; st <<= 1)
            #pragma unroll
            for (int c = 0; c < 16; c += 2 * st)
                s[c] += s[c + st];
        v = s[0];
    }

    // ---- publish partial, then pair ticket: last arriver combines ----
    g_partial[pair * 1024 + h * 512 + t] = v;   // coalesced 2KB store
    __shared__ unsigned s_last;
    __syncthreads();                            // all partial STGs issued
    if (t == 0) {
        unsigned my;
        asm volatile("atom.add.acq_rel.gpu.global.u32 %0, [%1], 1;"
                     : "=r"(my) : "l"(&g_tick[pair]) : "memory");
        s_last = my & 1u;                       // monotonic: wrap-safe on replays
    }
    __syncthreads();
    if (!s_last) return;                        // first arriver exits

    // last arriver: add peer k-half partial + bias, write output
    {
        float peer = g_partial[pair * 1024 + (1 - h) * 512 + t];
        int row = t >> 5, col = t & 31;
        out[(r0 + row) * NOUT + c0 + col] = (v + peer) + B[c0 + col];
    }
}

extern "C" void kernel_launch(void* const* d_in, const int* in_sizes, int n_in,
                              void* d_out, int out_size)
{
    const float* X = (const float*)d_in[0];  // (128, 1024)
    const float* W = (const float*)d_in[1];  // (1024, 512)
    const float* B = (const float*)d_in[2];  // (512,)
    float* out = (float*)d_out;              // (128, 512)

    cudaFuncSetAttribute(fused_kernel, cudaFuncAttributeMaxDynamicSharedMemorySize, SMEM_BYTES);
    fused_kernel<<<256, NTHR, SMEM_BYTES>>>(X, W, B, out);
}

// round 17
// speedup vs baseline: 1.2430x; 1.2430x over previous
#include <cuda_runtime.h>
#include <cuda_fp16.h>
#include <cstdint>

// y = x @ w + b  (exact collapse of the memristor model; G_off / K_V / k_g all
// cancel).  2-term fp16-split GEMM on mma.sync tensor cores:
//   y = xh@wh + xl@wh   (x = xh+xl exact: xh = 10-mantissa-bit truncation,
//   fp16-representable; only w-rounding error ~2e-4)
// Grid 128 = 8 row-blocks(16) x 16 col-blocks(32); full K=1024 per CTA.
// Fill = pure cp.async (24 fire-and-forget 16B ops/thread, fp32 staging in
// smem) -> DRAM fetch is bandwidth-parallel, not latency-serialized.
// fp32->fp16 conversion happens inside the fragment loads (registers).
// No atomics, no barriers, no scratch: intra-CTA smem tree reduce only.

#define NIN 1024
#define NOUT 512
#define BATCH 128
#define NTHR 512

#define XSTF 1032   // X staging row stride (floats); 4128B = 16B-multiple
#define WSTF 36     // W staging row stride (floats); 144B = 16B-multiple
#define RST  528    // reduce: 16x33 floats per warp

#define OFF_XS 0
#define OFF_WS (16 * XSTF)                    // 16512 floats
#define SMEM_FLOATS (OFF_WS + 1024 * WSTF)    // 53376 floats
#define SMEM_BYTES (SMEM_FLOATS * 4)          // 213504 B (<227KB opt-in)

__device__ __forceinline__ uint32_t packh(float a, float b) {
    __half2 h = __floats2half2_rn(a, b);      // a -> low 16 bits
    return *reinterpret_cast<uint32_t*>(&h);
}
__device__ __forceinline__ float trunc10(float x) {   // top 10 mantissa bits
    return __uint_as_float(__float_as_uint(x) & 0xFFFFE000u);
}
__device__ __forceinline__ void cp16(uint32_t smem_dst, const void* gmem_src) {
    asm volatile("cp.async.cg.shared.global [%0], [%1], 16;"
                 :: "r"(smem_dst), "l"(gmem_src));
}
__device__ __forceinline__ void mma_f16(float* c, const uint32_t* a, const uint32_t* b) {
    asm volatile(
        "mma.sync.aligned.m16n8k16.row.col.f32.f16.f16.f32 "
        "{%0,%1,%2,%3}, {%4,%5,%6,%7}, {%8,%9}, {%0,%1,%2,%3};"
        : "+f"(c[0]), "+f"(c[1]), "+f"(c[2]), "+f"(c[3])
        : "r"(a[0]), "r"(a[1]), "r"(a[2]), "r"(a[3]), "r"(b[0]), "r"(b[1]));
}

__global__ __launch_bounds__(NTHR) void fused_kernel(
    const float* __restrict__ X, const float* __restrict__ W,
    const float* __restrict__ B, float* __restrict__ out)
{
    extern __shared__ float sf[];
    float* Xs = sf + OFF_XS;                  // [16][XSTF] fp32
    float* Ws = sf + OFF_WS;                  // [1024][WSTF] fp32 (32 cols used)

    const int t = threadIdx.x, bid = blockIdx.x;
    const int warp = t >> 5, lane = t & 31;
    const int g  = lane >> 2;                 // group row 0..7
    const int tq = lane & 3;                  // thread-in-group 0..3
    const int r0 = (bid >> 4) * 16;           // row block 0..7
    const int c0 = (bid & 15) * 32;           // col block 0..15

    const uint32_t xs_u = (uint32_t)__cvta_generic_to_shared(Xs);
    const uint32_t ws_u = (uint32_t)__cvta_generic_to_shared(Ws);

    // ---- fill: pure cp.async, all 24 ops independent & in flight at once ----
    // X: 16 rows x 1024 floats = 4096 x 16B chunks (8 per thread)
    #pragma unroll
    for (int i = 0; i < 8; ++i) {
        int c = t + i * NTHR;                 // 0..4095
        int row = c >> 8, q = c & 255;        // q = 16B chunk within row
        cp16(xs_u + (row * XSTF + q * 4) * 4, &X[(r0 + row) * NIN + q * 4]);
    }
    // W: 1024 k-rows x 32 floats = 8192 x 16B chunks (16 per thread)
    #pragma unroll
    for (int i = 0; i < 16; ++i) {
        int c = t + i * NTHR;                 // 0..8191
        int k = c >> 3, q = c & 7;
        cp16(ws_u + (k * WSTF + q * 4) * 4, &W[k * NOUT + c0 + q * 4]);
    }
    asm volatile("cp.async.commit_group;" ::: "memory");
    asm volatile("cp.async.wait_group 0;" ::: "memory");
    __syncthreads();

    // ---- compute: warp = full 16x32 tile, k slice [warp*64, warp*64+64).
    //      Fragments converted fp32->fp16 in registers at load time. ----
    float acc[4][4];
    #pragma unroll
    for (int j = 0; j < 4; ++j)
        #pragma unroll
        for (int q = 0; q < 4; ++q) acc[j][q] = 0.f;

    const float* xr0 = &Xs[g * XSTF];
    const float* xr1 = &Xs[(g + 8) * XSTF];

    #pragma unroll
    for (int kk = 0; kk < 4; ++kk) {
        const int kb = warp * 64 + kk * 16 + 2 * tq;

        // A fragments: float2 per (row, k-pair); trunc10 split is exact.
        float2 x00 = *reinterpret_cast<const float2*>(&xr0[kb]);
        float2 x10 = *reinterpret_cast<const float2*>(&xr1[kb]);
        float2 x01 = *reinterpret_cast<const float2*>(&xr0[kb + 8]);
        float2 x11 = *reinterpret_cast<const float2*>(&xr1[kb + 8]);
        float a0 = trunc10(x00.x), a1 = trunc10(x00.y);
        float b0 = trunc10(x10.x), b1 = trunc10(x10.y);
        float c1 = trunc10(x01.x), c2 = trunc10(x01.y);
        float d0 = trunc10(x11.x), d1 = trunc10(x11.y);
        uint32_t ah[4], al[4];
        ah[0] = packh(a0, a1);  al[0] = packh(x00.x - a0, x00.y - a1);
        ah[1] = packh(b0, b1);  al[1] = packh(x10.x - b0, x10.y - b1);
        ah[2] = packh(c1, c2);  al[2] = packh(x01.x - c1, x01.y - c2);
        ah[3] = packh(d0, d1);  al[3] = packh(x11.x - d0, x11.y - d1);

        // B fragments: W[k][n] fp32 -> fp16 pairs.  Bank = 8tq+g+8j:
        // all 32 lanes distinct per load -> conflict-free.
        uint32_t bh[4][2];
        #pragma unroll
        for (int j = 0; j < 4; ++j) {
            int n = 8 * j + g;
            bh[j][0] = packh(Ws[kb * WSTF + n],       Ws[(kb + 1) * WSTF + n]);
            bh[j][1] = packh(Ws[(kb + 8) * WSTF + n], Ws[(kb + 9) * WSTF + n]);
        }
        #pragma unroll
        for (int j = 0; j < 4; ++j) mma_f16(acc[j], ah, bh[j]);
        #pragma unroll
        for (int j = 0; j < 4; ++j) mma_f16(acc[j], al, bh[j]);
    }

    // ---- intra-CTA reduce over the 16 k-slices (smem, fixed order) ----
    __syncthreads();                          // staging no longer read
    float* red = sf;                          // 16 warps x 528 floats = 33.8 KB
    #pragma unroll
    for (int j = 0; j < 4; ++j)
        #pragma unroll
        for (int q = 0; q < 4; ++q) {
            int row = g + 8 * (q >> 1);
            int col = 8 * j + 2 * tq + (q & 1);
            red[warp * RST + row * 33 + col] = acc[j][q];
        }
    __syncthreads();

    // each thread owns one output element of the 16x32 tile
    {
        int row = t >> 5, col = t & 31;
        float v[16];
        #pragma unroll
        for (int w = 0; w < 16; ++w)
            v[w] = red[w * RST + row * 33 + col];
        #pragma unroll
        for (int s = 1; s < 16; s <<= 1)
            #pragma unroll
            for (int c = 0; c < 16; c += 2 * s)
                v[c] += v[c + s];
        out[(r0 + row) * NOUT + c0 + col] = v[0] + B[c0 + col];
    }
}

extern "C" void kernel_launch(void* const* d_in, const int* in_sizes, int n_in,
                              void* d_out, int out_size)
{
    const float* X = (const float*)d_in[0];  // (128, 1024)
    const float* W = (const float*)d_in[1];  // (1024, 512)
    const float* B = (const float*)d_in[2];  // (512,)
    float* out = (float*)d_out;              // (128, 512)

    cudaFuncSetAttribute(fused_kernel, cudaFuncAttributeMaxDynamicSharedMemorySize, SMEM_BYTES);
    fused_kernel<<<128, NTHR, SMEM_BYTES>>>(X, W, B, out);
}